// round 10
// baseline (speedup 1.0000x reference)
#include <cuda_runtime.h>
#include <cuda_fp16.h>
#include <math.h>
#include <cstdint>

#define BB 2
#define SS 2048
#define DIM 4096
#define NH 32
#define NKV 8
#define HD 128
#define MR (BB*SS)          // 4096 rows
#define KVDIM (NKV*HD)      // 1024
#define SCALE 0.08838834764831845f   // 1/sqrt(128)

// ---- scratch (device globals; no allocation allowed) ----
__device__ __half g_qh[(size_t)MR * DIM];     // roped Q fp16 [b][h][s][d] (pre-scaled)
__device__ __half g_kh[(size_t)MR * KVDIM];   // roped K fp16 [b][kvh][s][d]
__device__ __half g_vh[(size_t)MR * KVDIM];   // V fp16 [b][kvh][s][d]
__device__ __half g_ath[(size_t)MR * DIM];    // attn out fp16 [row][h*128+d]
__device__ __half g_xh [(size_t)MR * DIM];    // fp16 copies of inputs
__device__ __half g_wqh[(size_t)DIM * DIM];
__device__ __half g_wkh[(size_t)KVDIM * DIM];
__device__ __half g_wvh[(size_t)KVDIM * DIM];
__device__ __half g_woh[(size_t)DIM * DIM];

// ============================================================
// helpers
// ============================================================
__device__ __forceinline__ uint32_t smem_u32(const void* p) {
    uint32_t a;
    asm("{ .reg .u64 t; cvta.to.shared.u64 t, %1; cvt.u32.u64 %0, t; }" : "=r"(a) : "l"(p));
    return a;
}
__device__ __forceinline__ void cpa16(uint32_t dst, const void* src) {
    asm volatile("cp.async.cg.shared.global [%0], [%1], 16;" :: "r"(dst), "l"(src));
}
#define CP_COMMIT asm volatile("cp.async.commit_group;")
#define CP_WAIT0  asm volatile("cp.async.wait_group 0;")
#define CP_WAIT1  asm volatile("cp.async.wait_group 1;")

__device__ __forceinline__ void ldsm4(uint32_t* r, uint32_t addr) {
    asm volatile("ldmatrix.sync.aligned.m8n8.x4.shared.b16 {%0,%1,%2,%3}, [%4];"
                 : "=r"(r[0]), "=r"(r[1]), "=r"(r[2]), "=r"(r[3]) : "r"(addr));
}
__device__ __forceinline__ void ldsm4t(uint32_t* r, uint32_t addr) {
    asm volatile("ldmatrix.sync.aligned.m8n8.x4.trans.shared.b16 {%0,%1,%2,%3}, [%4];"
                 : "=r"(r[0]), "=r"(r[1]), "=r"(r[2]), "=r"(r[3]) : "r"(addr));
}
__device__ __forceinline__ void mma16816(float* c, const uint32_t* a,
                                         uint32_t b0, uint32_t b1) {
    asm volatile(
        "mma.sync.aligned.m16n8k16.row.col.f32.f16.f16.f32 "
        "{%0,%1,%2,%3}, {%4,%5,%6,%7}, {%8,%9}, {%0,%1,%2,%3};\n"
        : "+f"(c[0]), "+f"(c[1]), "+f"(c[2]), "+f"(c[3])
        : "r"(a[0]), "r"(a[1]), "r"(a[2]), "r"(a[3]), "r"(b0), "r"(b1));
}
__device__ __forceinline__ uint32_t packh2(float a, float b) {
    __half2 h = __floats2half2_rn(a, b);
    return *(uint32_t*)&h;
}

// ============================================================
// fp32 -> fp16 convert
// ============================================================
__global__ void cvt_h(const float* __restrict__ in, __half* __restrict__ out, int n2) {
    int i = blockIdx.x * blockDim.x + threadIdx.x;
    if (i < n2) {
        float2 v = ((const float2*)in)[i];
        ((__half2*)out)[i] = __floats2half2_rn(v.x, v.y);
    }
}

// ============================================================
// fp16 HMMA NT GEMM, 3-stage cp.async pipeline, fused epilogues.
// C[M,N] = A[M,K]*B[N,K]^T.  BM=BN=128, BK=32, 256 thr, warp tile 32x64.
// EPI: 0 = fp32 C row-major (wo proj)
//      1 = RoPE + scale -> fp16 [b][h(NH)][s][d]   (Q proj)
//      2 = RoPE        -> fp16 [b][h(NKV)][s][d]   (K proj)
//      3 = transpose   -> fp16 [b][h(NKV)][s][d]   (V proj)
// ============================================================
#define LDH 40   // halves per smem row (32 data + 8 pad)
#define TILEH (128 * LDH)          // halves per tile
#define GEMM_SMEM (6 * TILEH * 2)  // 3 stages x (A+B), bytes = 61440

template<int EPI>
__global__ __launch_bounds__(256, 2)
void gemm3(const __half* __restrict__ A, const __half* __restrict__ Bw,
           float* __restrict__ C, __half* __restrict__ Ch,
           const float* __restrict__ fc, const float* __restrict__ fs,
           int M, int N, int K) {
    extern __shared__ __half smg[];
    const int t = threadIdx.x;
    const int bm = blockIdx.y * 128, bn = blockIdx.x * 128;
    const int lane = t & 31, warp = t >> 5;
    const int wm = (warp >> 1) * 32, wn = (warp & 1) * 64;

    const int r0 = t >> 2, c0 = t & 3;
    const int r1 = (t + 256) >> 2;
    const __half* Ag = A  + (size_t)bm * K;
    const __half* Bg = Bw + (size_t)bn * K;

    uint32_t sa[3], sb[3];
    #pragma unroll
    for (int i = 0; i < 3; i++) {
        sa[i] = smem_u32(smg + i * TILEH);
        sb[i] = smem_u32(smg + (3 + i) * TILEH);
    }

#define FILLT(buf, kt) do {                                                        \
    uint32_t _a = sa[buf], _b = sb[buf];                                           \
    const __half* _Ak = Ag + (kt) * 32;                                            \
    const __half* _Bk = Bg + (kt) * 32;                                            \
    cpa16(_a + (r0 * LDH + c0 * 8) * 2, _Ak + (size_t)r0 * K + c0 * 8);            \
    cpa16(_a + (r1 * LDH + c0 * 8) * 2, _Ak + (size_t)r1 * K + c0 * 8);            \
    cpa16(_b + (r0 * LDH + c0 * 8) * 2, _Bk + (size_t)r0 * K + c0 * 8);            \
    cpa16(_b + (r1 * LDH + c0 * 8) * 2, _Bk + (size_t)r1 * K + c0 * 8);            \
    CP_COMMIT; } while (0)

    float acc[2][8][4];
    #pragma unroll
    for (int mi = 0; mi < 2; mi++)
        #pragma unroll
        for (int ni = 0; ni < 8; ni++)
            #pragma unroll
            for (int j = 0; j < 4; j++) acc[mi][ni][j] = 0.f;

    const int niter = K >> 5;
    FILLT(0, 0);
    FILLT(1, 1);

    int buf = 0;
    for (int it = 0; it < niter; it++) {
        CP_WAIT1;
        __syncthreads();
        if (it + 2 < niter) {
            int nb = buf + 2; if (nb >= 3) nb -= 3;
            FILLT(nb, it + 2);
        }

        const uint32_t pa = sa[buf], pb = sb[buf];
        #pragma unroll
        for (int ks = 0; ks < 2; ks++) {
            uint32_t a[2][4];
            #pragma unroll
            for (int mi = 0; mi < 2; mi++) {
                uint32_t addr = pa + (((wm + mi * 16 + (lane & 15)) * LDH) +
                                      (2 * ks + (lane >> 4)) * 8) * 2;
                ldsm4(a[mi], addr);
            }
            uint32_t b[4][4];
            #pragma unroll
            for (int np = 0; np < 4; np++) {
                uint32_t addr = pb + (((wn + np * 16 + (lane & 15)) * LDH) +
                                      (2 * ks + (lane >> 4)) * 8) * 2;
                ldsm4(b[np], addr);
            }
            #pragma unroll
            for (int mi = 0; mi < 2; mi++)
                #pragma unroll
                for (int np = 0; np < 4; np++) {
                    mma16816(acc[mi][np * 2],     a[mi], b[np][0], b[np][2]);
                    mma16816(acc[mi][np * 2 + 1], a[mi], b[np][1], b[np][3]);
                }
        }
        if (++buf == 3) buf = 0;
    }

    const int g = lane >> 2, l4 = lane & 3;
    if (EPI == 0) {
        #pragma unroll
        for (int mi = 0; mi < 2; mi++)
            #pragma unroll
            for (int ni = 0; ni < 8; ni++) {
                const int rr = bm + wm + mi * 16 + g;
                const int cc = bn + wn + ni * 8 + l4 * 2;
                *(float2*)&C[(size_t)rr * N + cc]       = make_float2(acc[mi][ni][0], acc[mi][ni][1]);
                *(float2*)&C[(size_t)(rr + 8) * N + cc] = make_float2(acc[mi][ni][2], acc[mi][ni][3]);
            }
    } else {
        const int nh = (EPI == 1) ? NH : NKV;
        #pragma unroll
        for (int mi = 0; mi < 2; mi++)
            #pragma unroll
            for (int ni = 0; ni < 8; ni++) {
                const int rr = bm + wm + mi * 16 + g;
                const int cc = bn + wn + ni * 8 + l4 * 2;
                const int hh = cc >> 7, d = cc & 127, p = d >> 1;
                #pragma unroll
                for (int hf = 0; hf < 2; hf++) {
                    const int row = rr + 8 * hf;
                    const int s = row & (SS - 1), b = row >> 11;
                    float x0 = acc[mi][ni][2 * hf], x1 = acc[mi][ni][2 * hf + 1];
                    if (EPI != 3) {
                        float cv = fc[s * 64 + p], sv = fs[s * 64 + p];
                        float y0 = x0 * cv - x1 * sv;
                        float y1 = x0 * sv + x1 * cv;
                        if (EPI == 1) { y0 *= SCALE; y1 *= SCALE; }
                        x0 = y0; x1 = y1;
                    }
                    *(__half2*)&Ch[(((size_t)(b * nh + hh)) * SS + s) * HD + d] =
                        __floats2half2_rn(x0, x1);
                }
            }
    }
}

// ============================================================
// fp16 HMMA flash attention (unchanged from R8, passing).
// Q tile 128 (8 warps x 16 rows), KV tile 64, double-buffered K/V.
// ============================================================
#define QT 128
#define KT 64
#define LDK 136
#define STGH (2 * KT * LDK)

__global__ __launch_bounds__(256, 1)
void attn_h16(const __half* __restrict__ Q, const __half* __restrict__ K,
              const __half* __restrict__ V, __half* __restrict__ O) {
    extern __shared__ __half sm[];
    const int t = threadIdx.x, lane = t & 31, w = t >> 5;
    const int l4 = lane & 3, g = lane >> 2, lr = lane & 15, lc = lane >> 4;
    const int qt = blockIdx.x, h = blockIdx.y, b = blockIdx.z;
    const int kvh = h >> 2, q0 = qt * QT;
    const __half* qg = Q + ((size_t)(b * NH + h) * SS + q0) * HD;
    const __half* kg = K + ((size_t)(b * NKV + kvh) * SS) * HD;
    const __half* vg = V + ((size_t)(b * NKV + kvh) * SS) * HD;
    const uint32_t smb = smem_u32(sm);
    const uint32_t qsm = smb + 2 * STGH * 2;

    for (int i = t; i < 2048; i += 256) {
        int r = i >> 4, c = i & 15;
        cpa16(qsm + (r * LDK + c * 8) * 2, qg + (size_t)r * HD + c * 8);
    }
    CP_COMMIT;

#define LOADKV(tile, buf) do {                                                  \
    uint32_t _k = smb + (buf) * STGH * 2;                                       \
    uint32_t _v = _k + KT * LDK * 2;                                            \
    const __half* _gk = kg + (size_t)(tile) * KT * HD;                          \
    const __half* _gv = vg + (size_t)(tile) * KT * HD;                          \
    _Pragma("unroll")                                                           \
    for (int _i = 0; _i < 4; _i++) {                                            \
        int _id = _i * 256 + t; int _r = _id >> 4, _c = _id & 15;               \
        cpa16(_k + (_r * LDK + _c * 8) * 2, _gk + (size_t)_r * HD + _c * 8);    \
        cpa16(_v + (_r * LDK + _c * 8) * 2, _gv + (size_t)_r * HD + _c * 8);    \
    }                                                                           \
    CP_COMMIT; } while (0)

    const int ntiles = q0 / KT + 2;
    LOADKV(0, 0);

    CP_WAIT1;
    __syncthreads();

    uint32_t qf_[8][4];
    #pragma unroll
    for (int ks = 0; ks < 8; ks++)
        ldsm4(qf_[ks], qsm + ((w * 16 + lr) * LDK + ks * 16 + lc * 8) * 2);

    if (ntiles > 1) LOADKV(1, 1);

    float mx0 = -INFINITY, mx1 = -INFINITY, l0 = 0.f, l1 = 0.f;
    float oacc[16][4];
    #pragma unroll
    for (int j = 0; j < 16; j++)
        #pragma unroll
        for (int e = 0; e < 4; e++) oacc[j][e] = 0.f;

    for (int it = 0; it < ntiles; it++) {
        if (it + 1 < ntiles) { CP_WAIT1; } else { CP_WAIT0; }
        __syncthreads();
        const uint32_t bK = smb + (it & 1) * STGH * 2;
        const uint32_t bV = bK + KT * LDK * 2;
        const int kv0 = it * KT;

        float sc[8][4];
        #pragma unroll
        for (int f = 0; f < 8; f++)
            #pragma unroll
            for (int e = 0; e < 4; e++) sc[f][e] = 0.f;

        #pragma unroll
        for (int ks = 0; ks < 8; ks++) {
            #pragma unroll
            for (int np = 0; np < 4; np++) {
                uint32_t kb4[4];
                ldsm4(kb4, bK + ((np * 16 + lr) * LDK + ks * 16 + lc * 8) * 2);
                mma16816(sc[2 * np],     qf_[ks], kb4[0], kb4[2]);
                mma16816(sc[2 * np + 1], qf_[ks], kb4[1], kb4[3]);
            }
        }

        const int row0 = q0 + w * 16 + g;
        if (kv0 + KT - 1 > q0 + w * 16) {
            #pragma unroll
            for (int f = 0; f < 8; f++) {
                int c = kv0 + 8 * f + l4 * 2;
                if (c     > row0)     sc[f][0] = -1e30f;
                if (c + 1 > row0)     sc[f][1] = -1e30f;
                if (c     > row0 + 8) sc[f][2] = -1e30f;
                if (c + 1 > row0 + 8) sc[f][3] = -1e30f;
            }
        }

        float m0 = -INFINITY, m1 = -INFINITY;
        #pragma unroll
        for (int f = 0; f < 8; f++) {
            m0 = fmaxf(m0, fmaxf(sc[f][0], sc[f][1]));
            m1 = fmaxf(m1, fmaxf(sc[f][2], sc[f][3]));
        }
        m0 = fmaxf(m0, __shfl_xor_sync(0xffffffffu, m0, 1));
        m0 = fmaxf(m0, __shfl_xor_sync(0xffffffffu, m0, 2));
        m1 = fmaxf(m1, __shfl_xor_sync(0xffffffffu, m1, 1));
        m1 = fmaxf(m1, __shfl_xor_sync(0xffffffffu, m1, 2));
        float nm0 = fmaxf(mx0, m0), nm1 = fmaxf(mx1, m1);
        float cs0 = __expf(mx0 - nm0), cs1 = __expf(mx1 - nm1);
        mx0 = nm0; mx1 = nm1;

        float ps0 = 0.f, ps1 = 0.f;
        #pragma unroll
        for (int f = 0; f < 8; f++) {
            sc[f][0] = __expf(sc[f][0] - nm0);
            sc[f][1] = __expf(sc[f][1] - nm0);
            sc[f][2] = __expf(sc[f][2] - nm1);
            sc[f][3] = __expf(sc[f][3] - nm1);
            ps0 += sc[f][0] + sc[f][1];
            ps1 += sc[f][2] + sc[f][3];
        }
        l0 = l0 * cs0 + ps0;
        l1 = l1 * cs1 + ps1;
        #pragma unroll
        for (int j = 0; j < 16; j++) {
            oacc[j][0] *= cs0; oacc[j][1] *= cs0;
            oacc[j][2] *= cs1; oacc[j][3] *= cs1;
        }

        uint32_t pf[4][4];
        #pragma unroll
        for (int kb = 0; kb < 4; kb++) {
            pf[kb][0] = packh2(sc[2 * kb][0],     sc[2 * kb][1]);
            pf[kb][1] = packh2(sc[2 * kb][2],     sc[2 * kb][3]);
            pf[kb][2] = packh2(sc[2 * kb + 1][0], sc[2 * kb + 1][1]);
            pf[kb][3] = packh2(sc[2 * kb + 1][2], sc[2 * kb + 1][3]);
        }

        #pragma unroll
        for (int kb = 0; kb < 4; kb++) {
            #pragma unroll
            for (int dj = 0; dj < 8; dj++) {
                uint32_t vb[4];
                ldsm4t(vb, bV + ((kb * 16 + lr) * LDK + dj * 16 + lc * 8) * 2);
                mma16816(oacc[2 * dj],     pf[kb], vb[0], vb[1]);
                mma16816(oacc[2 * dj + 1], pf[kb], vb[2], vb[3]);
            }
        }

        __syncthreads();
        if (it + 2 < ntiles) LOADKV(it + 2, it & 1);
    }

    l0 += __shfl_xor_sync(0xffffffffu, l0, 1);
    l0 += __shfl_xor_sync(0xffffffffu, l0, 2);
    l1 += __shfl_xor_sync(0xffffffffu, l1, 1);
    l1 += __shfl_xor_sync(0xffffffffu, l1, 2);
    float inv0 = 1.f / l0, inv1 = 1.f / l1;

    const int row0 = q0 + w * 16 + g;
    __half* o0 = O + ((size_t)(b * SS) + row0) * DIM + h * HD;
    __half* o1 = o0 + (size_t)8 * DIM;
    #pragma unroll
    for (int j = 0; j < 16; j++) {
        int col = 8 * j + l4 * 2;
        *(__half2*)&o0[col] = __floats2half2_rn(oacc[j][0] * inv0, oacc[j][1] * inv0);
        *(__half2*)&o1[col] = __floats2half2_rn(oacc[j][2] * inv1, oacc[j][3] * inv1);
    }
}

// ============================================================
extern "C" void kernel_launch(void* const* d_in, const int* in_sizes, int n_in,
                              void* d_out, int out_size) {
    const float* x  = (const float*)d_in[0];
    const float* wq = (const float*)d_in[1];
    const float* wk = (const float*)d_in[2];
    const float* wv = (const float*)d_in[3];
    const float* wo = (const float*)d_in[4];
    const float* fc = (const float*)d_in[5];
    const float* fs = (const float*)d_in[6];
    float* out = (float*)d_out;

    __half *qh, *kh, *vh, *ath, *xh, *wqh, *wkh, *wvh, *woh;
    cudaGetSymbolAddress((void**)&qh,  g_qh);
    cudaGetSymbolAddress((void**)&kh,  g_kh);
    cudaGetSymbolAddress((void**)&vh,  g_vh);
    cudaGetSymbolAddress((void**)&ath, g_ath);
    cudaGetSymbolAddress((void**)&xh,  g_xh);
    cudaGetSymbolAddress((void**)&wqh, g_wqh);
    cudaGetSymbolAddress((void**)&wkh, g_wkh);
    cudaGetSymbolAddress((void**)&wvh, g_wvh);
    cudaGetSymbolAddress((void**)&woh, g_woh);

    const int ATTN_SMEM = (2 * STGH + QT * LDK) * 2;   // 104448 bytes
    cudaFuncSetAttribute(attn_h16, cudaFuncAttributeMaxDynamicSharedMemorySize, ATTN_SMEM);
    cudaFuncSetAttribute(gemm3<0>, cudaFuncAttributeMaxDynamicSharedMemorySize, GEMM_SMEM);
    cudaFuncSetAttribute(gemm3<1>, cudaFuncAttributeMaxDynamicSharedMemorySize, GEMM_SMEM);
    cudaFuncSetAttribute(gemm3<2>, cudaFuncAttributeMaxDynamicSharedMemorySize, GEMM_SMEM);
    cudaFuncSetAttribute(gemm3<3>, cudaFuncAttributeMaxDynamicSharedMemorySize, GEMM_SMEM);

    // fp16 copies
    cvt_h<<<(MR * DIM / 2 + 255) / 256, 256>>>(x,  xh,  MR * DIM / 2);
    cvt_h<<<((size_t)DIM * DIM / 2 + 255) / 256, 256>>>(wq, wqh, DIM * DIM / 2);
    cvt_h<<<((size_t)KVDIM * DIM / 2 + 255) / 256, 256>>>(wk, wkh, KVDIM * DIM / 2);
    cvt_h<<<((size_t)KVDIM * DIM / 2 + 255) / 256, 256>>>(wv, wvh, KVDIM * DIM / 2);
    cvt_h<<<((size_t)DIM * DIM / 2 + 255) / 256, 256>>>(wo, woh, DIM * DIM / 2);

    // QKV projections with fused RoPE/transpose epilogues
    gemm3<1><<<dim3(DIM / 128,   MR / 128), 256, GEMM_SMEM>>>(xh, wqh, nullptr, qh, fc, fs, MR, DIM,   DIM);
    gemm3<2><<<dim3(KVDIM / 128, MR / 128), 256, GEMM_SMEM>>>(xh, wkh, nullptr, kh, fc, fs, MR, KVDIM, DIM);
    gemm3<3><<<dim3(KVDIM / 128, MR / 128), 256, GEMM_SMEM>>>(xh, wvh, nullptr, vh, fc, fs, MR, KVDIM, DIM);

    // causal GQA attention (fp16 HMMA, fp32 softmax)
    attn_h16<<<dim3(SS / QT, NH, BB), 256, ATTN_SMEM>>>(qh, kh, vh, ath);

    // output projection (fp32 epilogue to d_out)
    gemm3<0><<<dim3(DIM / 128, MR / 128), 256, GEMM_SMEM>>>(ath, woh, out, nullptr, nullptr, nullptr, MR, DIM, DIM);
}

// round 12
// speedup vs baseline: 1.4835x; 1.4835x over previous
#include <cuda_runtime.h>
#include <cuda_fp16.h>
#include <math.h>
#include <cstdint>

#define BB 2
#define SS 2048
#define DIM 4096
#define NH 32
#define NKV 8
#define HD 128
#define MR (BB*SS)          // 4096 rows
#define KVDIM (NKV*HD)      // 1024
#define SCALE 0.08838834764831845f   // 1/sqrt(128)

// ---- scratch (device globals; no allocation allowed) ----
__device__ __half g_qh[(size_t)MR * DIM];     // roped Q fp16 [b][h][s][d] (pre-scaled)
__device__ __half g_kh[(size_t)MR * KVDIM];   // roped K fp16 [b][kvh][s][d]
__device__ __half g_vh[(size_t)MR * KVDIM];   // V fp16 [b][kvh][s][d]
__device__ __half g_ath[(size_t)MR * DIM];    // attn out fp16 [row][h*128+d]
__device__ __half g_xh [(size_t)MR * DIM];    // fp16 copies of inputs
__device__ __half g_wqh[(size_t)DIM * DIM];
__device__ __half g_wkh[(size_t)KVDIM * DIM];
__device__ __half g_wvh[(size_t)KVDIM * DIM];
__device__ __half g_woh[(size_t)DIM * DIM];

// ============================================================
// helpers
// ============================================================
__device__ __forceinline__ uint32_t smem_u32(const void* p) {
    uint32_t a;
    asm("{ .reg .u64 t; cvta.to.shared.u64 t, %1; cvt.u32.u64 %0, t; }" : "=r"(a) : "l"(p));
    return a;
}
__device__ __forceinline__ void cpa16(uint32_t dst, const void* src) {
    asm volatile("cp.async.cg.shared.global [%0], [%1], 16;" :: "r"(dst), "l"(src));
}
#define CP_COMMIT asm volatile("cp.async.commit_group;")
#define CP_WAIT0  asm volatile("cp.async.wait_group 0;")
#define CP_WAIT1  asm volatile("cp.async.wait_group 1;")

__device__ __forceinline__ void ldsm4(uint32_t* r, uint32_t addr) {
    asm volatile("ldmatrix.sync.aligned.m8n8.x4.shared.b16 {%0,%1,%2,%3}, [%4];"
                 : "=r"(r[0]), "=r"(r[1]), "=r"(r[2]), "=r"(r[3]) : "r"(addr));
}
__device__ __forceinline__ void ldsm4t(uint32_t* r, uint32_t addr) {
    asm volatile("ldmatrix.sync.aligned.m8n8.x4.trans.shared.b16 {%0,%1,%2,%3}, [%4];"
                 : "=r"(r[0]), "=r"(r[1]), "=r"(r[2]), "=r"(r[3]) : "r"(addr));
}
__device__ __forceinline__ void mma16816(float* c, const uint32_t* a,
                                         uint32_t b0, uint32_t b1) {
    asm volatile(
        "mma.sync.aligned.m16n8k16.row.col.f32.f16.f16.f32 "
        "{%0,%1,%2,%3}, {%4,%5,%6,%7}, {%8,%9}, {%0,%1,%2,%3};\n"
        : "+f"(c[0]), "+f"(c[1]), "+f"(c[2]), "+f"(c[3])
        : "r"(a[0]), "r"(a[1]), "r"(a[2]), "r"(a[3]), "r"(b0), "r"(b1));
}
__device__ __forceinline__ uint32_t packh2(float a, float b) {
    __half2 h = __floats2half2_rn(a, b);
    return *(uint32_t*)&h;
}

// ============================================================
// fp32 -> fp16 convert
// ============================================================
__global__ void cvt_h(const float* __restrict__ in, __half* __restrict__ out, int n2) {
    int i = blockIdx.x * blockDim.x + threadIdx.x;
    if (i < n2) {
        float2 v = ((const float2*)in)[i];
        ((__half2*)out)[i] = __floats2half2_rn(v.x, v.y);
    }
}

// ============================================================
// fp16 HMMA NT GEMM — EXACT R8 mainloop (2-stage, static smem).
// Fused epilogues:
//   EPI 0 = fp32 C row-major (wo proj)
//   EPI 1 = RoPE + scale -> fp16 [b][h(NH)][s][d]   (Q proj)
//   EPI 2 = RoPE         -> fp16 [b][h(NKV)][s][d]  (K proj)
//   EPI 3 = transpose    -> fp16 [b][h(NKV)][s][d]  (V proj)
// ============================================================
#define LDH 40

template<int EPI>
__global__ __launch_bounds__(256, 2)
void gemm_f(const __half* __restrict__ A, const __half* __restrict__ Bw,
            float* __restrict__ C, __half* __restrict__ Ch,
            const float* __restrict__ fc, const float* __restrict__ fs,
            int M, int N, int K) {
    __shared__ __half As[2][128 * LDH];
    __shared__ __half Bs[2][128 * LDH];
    const int t = threadIdx.x;
    const int bm = blockIdx.y * 128, bn = blockIdx.x * 128;
    const int lane = t & 31, warp = t >> 5;
    const int wm = (warp >> 1) * 32, wn = (warp & 1) * 64;

    const int r0 = t >> 2, c0 = t & 3;
    const int r1 = (t + 256) >> 2;
    const __half* Ag = A  + (size_t)bm * K;
    const __half* Bg = Bw + (size_t)bn * K;

    const uint32_t sa[2] = { smem_u32(&As[0][0]), smem_u32(&As[1][0]) };
    const uint32_t sb[2] = { smem_u32(&Bs[0][0]), smem_u32(&Bs[1][0]) };

#define FILLT(buf, kt) do {                                                        \
    uint32_t _a = sa[buf], _b = sb[buf];                                           \
    const __half* _Ak = Ag + (kt) * 32;                                            \
    const __half* _Bk = Bg + (kt) * 32;                                            \
    cpa16(_a + (r0 * LDH + c0 * 8) * 2, _Ak + (size_t)r0 * K + c0 * 8);            \
    cpa16(_a + (r1 * LDH + c0 * 8) * 2, _Ak + (size_t)r1 * K + c0 * 8);            \
    cpa16(_b + (r0 * LDH + c0 * 8) * 2, _Bk + (size_t)r0 * K + c0 * 8);            \
    cpa16(_b + (r1 * LDH + c0 * 8) * 2, _Bk + (size_t)r1 * K + c0 * 8);            \
    CP_COMMIT; } while (0)

    float acc[2][8][4];
    #pragma unroll
    for (int mi = 0; mi < 2; mi++)
        #pragma unroll
        for (int ni = 0; ni < 8; ni++)
            #pragma unroll
            for (int j = 0; j < 4; j++) acc[mi][ni][j] = 0.f;

    const int niter = K >> 5;
    FILLT(0, 0);

    for (int it = 0; it < niter; it++) {
        const int buf = it & 1;
        CP_WAIT0;
        __syncthreads();
        if (it + 1 < niter) FILLT(buf ^ 1, it + 1);

        const uint32_t pa = sa[buf], pb = sb[buf];

        #pragma unroll
        for (int ks = 0; ks < 2; ks++) {
            uint32_t a[2][4];
            #pragma unroll
            for (int mi = 0; mi < 2; mi++) {
                uint32_t addr = pa + (((wm + mi * 16 + (lane & 15)) * LDH) +
                                      (2 * ks + (lane >> 4)) * 8) * 2;
                ldsm4(a[mi], addr);
            }
            uint32_t b[4][4];
            #pragma unroll
            for (int np = 0; np < 4; np++) {
                uint32_t addr = pb + (((wn + np * 16 + (lane & 15)) * LDH) +
                                      (2 * ks + (lane >> 4)) * 8) * 2;
                ldsm4(b[np], addr);
            }
            #pragma unroll
            for (int mi = 0; mi < 2; mi++)
                #pragma unroll
                for (int np = 0; np < 4; np++) {
                    mma16816(acc[mi][np * 2],     a[mi], b[np][0], b[np][2]);
                    mma16816(acc[mi][np * 2 + 1], a[mi], b[np][1], b[np][3]);
                }
        }
        __syncthreads();
    }

    const int g = lane >> 2, l4 = lane & 3;
    if (EPI == 0) {
        #pragma unroll
        for (int mi = 0; mi < 2; mi++)
            #pragma unroll
            for (int ni = 0; ni < 8; ni++) {
                const int rr = bm + wm + mi * 16 + g;
                const int cc = bn + wn + ni * 8 + l4 * 2;
                *(float2*)&C[(size_t)rr * N + cc]       = make_float2(acc[mi][ni][0], acc[mi][ni][1]);
                *(float2*)&C[(size_t)(rr + 8) * N + cc] = make_float2(acc[mi][ni][2], acc[mi][ni][3]);
            }
    } else {
        const int nh = (EPI == 1) ? NH : NKV;
        #pragma unroll
        for (int mi = 0; mi < 2; mi++)
            #pragma unroll
            for (int ni = 0; ni < 8; ni++) {
                const int rr = bm + wm + mi * 16 + g;
                const int cc = bn + wn + ni * 8 + l4 * 2;
                const int hh = cc >> 7, d = cc & 127, p = d >> 1;
                #pragma unroll
                for (int hf = 0; hf < 2; hf++) {
                    const int row = rr + 8 * hf;
                    const int s = row & (SS - 1), b = row >> 11;
                    float x0 = acc[mi][ni][2 * hf], x1 = acc[mi][ni][2 * hf + 1];
                    if (EPI != 3) {
                        float cv = fc[s * 64 + p], sv = fs[s * 64 + p];
                        float y0 = x0 * cv - x1 * sv;
                        float y1 = x0 * sv + x1 * cv;
                        if (EPI == 1) { y0 *= SCALE; y1 *= SCALE; }
                        x0 = y0; x1 = y1;
                    }
                    *(__half2*)&Ch[(((size_t)(b * nh + hh)) * SS + s) * HD + d] =
                        __floats2half2_rn(x0, x1);
                }
            }
    }
}

// ============================================================
// fp16 HMMA flash attention (unchanged from R8, passing).
// Q tile 128 (8 warps x 16 rows), KV tile 64, double-buffered K/V.
// ============================================================
#define QT 128
#define KT 64
#define LDK 136
#define STGH (2 * KT * LDK)

__global__ __launch_bounds__(256, 1)
void attn_h16(const __half* __restrict__ Q, const __half* __restrict__ K,
              const __half* __restrict__ V, __half* __restrict__ O) {
    extern __shared__ __half sm[];
    const int t = threadIdx.x, lane = t & 31, w = t >> 5;
    const int l4 = lane & 3, g = lane >> 2, lr = lane & 15, lc = lane >> 4;
    const int qt = blockIdx.x, h = blockIdx.y, b = blockIdx.z;
    const int kvh = h >> 2, q0 = qt * QT;
    const __half* qg = Q + ((size_t)(b * NH + h) * SS + q0) * HD;
    const __half* kg = K + ((size_t)(b * NKV + kvh) * SS) * HD;
    const __half* vg = V + ((size_t)(b * NKV + kvh) * SS) * HD;
    const uint32_t smb = smem_u32(sm);
    const uint32_t qsm = smb + 2 * STGH * 2;

    for (int i = t; i < 2048; i += 256) {
        int r = i >> 4, c = i & 15;
        cpa16(qsm + (r * LDK + c * 8) * 2, qg + (size_t)r * HD + c * 8);
    }
    CP_COMMIT;

#define LOADKV(tile, buf) do {                                                  \
    uint32_t _k = smb + (buf) * STGH * 2;                                       \
    uint32_t _v = _k + KT * LDK * 2;                                            \
    const __half* _gk = kg + (size_t)(tile) * KT * HD;                          \
    const __half* _gv = vg + (size_t)(tile) * KT * HD;                          \
    _Pragma("unroll")                                                           \
    for (int _i = 0; _i < 4; _i++) {                                            \
        int _id = _i * 256 + t; int _r = _id >> 4, _c = _id & 15;               \
        cpa16(_k + (_r * LDK + _c * 8) * 2, _gk + (size_t)_r * HD + _c * 8);    \
        cpa16(_v + (_r * LDK + _c * 8) * 2, _gv + (size_t)_r * HD + _c * 8);    \
    }                                                                           \
    CP_COMMIT; } while (0)

    const int ntiles = q0 / KT + 2;
    LOADKV(0, 0);

    CP_WAIT1;
    __syncthreads();

    uint32_t qf_[8][4];
    #pragma unroll
    for (int ks = 0; ks < 8; ks++)
        ldsm4(qf_[ks], qsm + ((w * 16 + lr) * LDK + ks * 16 + lc * 8) * 2);

    if (ntiles > 1) LOADKV(1, 1);

    float mx0 = -INFINITY, mx1 = -INFINITY, l0 = 0.f, l1 = 0.f;
    float oacc[16][4];
    #pragma unroll
    for (int j = 0; j < 16; j++)
        #pragma unroll
        for (int e = 0; e < 4; e++) oacc[j][e] = 0.f;

    for (int it = 0; it < ntiles; it++) {
        if (it + 1 < ntiles) { CP_WAIT1; } else { CP_WAIT0; }
        __syncthreads();
        const uint32_t bK = smb + (it & 1) * STGH * 2;
        const uint32_t bV = bK + KT * LDK * 2;
        const int kv0 = it * KT;

        float sc[8][4];
        #pragma unroll
        for (int f = 0; f < 8; f++)
            #pragma unroll
            for (int e = 0; e < 4; e++) sc[f][e] = 0.f;

        #pragma unroll
        for (int ks = 0; ks < 8; ks++) {
            #pragma unroll
            for (int np = 0; np < 4; np++) {
                uint32_t kb4[4];
                ldsm4(kb4, bK + ((np * 16 + lr) * LDK + ks * 16 + lc * 8) * 2);
                mma16816(sc[2 * np],     qf_[ks], kb4[0], kb4[2]);
                mma16816(sc[2 * np + 1], qf_[ks], kb4[1], kb4[3]);
            }
        }

        const int row0 = q0 + w * 16 + g;
        if (kv0 + KT - 1 > q0 + w * 16) {
            #pragma unroll
            for (int f = 0; f < 8; f++) {
                int c = kv0 + 8 * f + l4 * 2;
                if (c     > row0)     sc[f][0] = -1e30f;
                if (c + 1 > row0)     sc[f][1] = -1e30f;
                if (c     > row0 + 8) sc[f][2] = -1e30f;
                if (c + 1 > row0 + 8) sc[f][3] = -1e30f;
            }
        }

        float m0 = -INFINITY, m1 = -INFINITY;
        #pragma unroll
        for (int f = 0; f < 8; f++) {
            m0 = fmaxf(m0, fmaxf(sc[f][0], sc[f][1]));
            m1 = fmaxf(m1, fmaxf(sc[f][2], sc[f][3]));
        }
        m0 = fmaxf(m0, __shfl_xor_sync(0xffffffffu, m0, 1));
        m0 = fmaxf(m0, __shfl_xor_sync(0xffffffffu, m0, 2));
        m1 = fmaxf(m1, __shfl_xor_sync(0xffffffffu, m1, 1));
        m1 = fmaxf(m1, __shfl_xor_sync(0xffffffffu, m1, 2));
        float nm0 = fmaxf(mx0, m0), nm1 = fmaxf(mx1, m1);
        float cs0 = __expf(mx0 - nm0), cs1 = __expf(mx1 - nm1);
        mx0 = nm0; mx1 = nm1;

        float ps0 = 0.f, ps1 = 0.f;
        #pragma unroll
        for (int f = 0; f < 8; f++) {
            sc[f][0] = __expf(sc[f][0] - nm0);
            sc[f][1] = __expf(sc[f][1] - nm0);
            sc[f][2] = __expf(sc[f][2] - nm1);
            sc[f][3] = __expf(sc[f][3] - nm1);
            ps0 += sc[f][0] + sc[f][1];
            ps1 += sc[f][2] + sc[f][3];
        }
        l0 = l0 * cs0 + ps0;
        l1 = l1 * cs1 + ps1;
        #pragma unroll
        for (int j = 0; j < 16; j++) {
            oacc[j][0] *= cs0; oacc[j][1] *= cs0;
            oacc[j][2] *= cs1; oacc[j][3] *= cs1;
        }

        uint32_t pf[4][4];
        #pragma unroll
        for (int kb = 0; kb < 4; kb++) {
            pf[kb][0] = packh2(sc[2 * kb][0],     sc[2 * kb][1]);
            pf[kb][1] = packh2(sc[2 * kb][2],     sc[2 * kb][3]);
            pf[kb][2] = packh2(sc[2 * kb + 1][0], sc[2 * kb + 1][1]);
            pf[kb][3] = packh2(sc[2 * kb + 1][2], sc[2 * kb + 1][3]);
        }

        #pragma unroll
        for (int kb = 0; kb < 4; kb++) {
            #pragma unroll
            for (int dj = 0; dj < 8; dj++) {
                uint32_t vb[4];
                ldsm4t(vb, bV + ((kb * 16 + lr) * LDK + dj * 16 + lc * 8) * 2);
                mma16816(oacc[2 * dj],     pf[kb], vb[0], vb[1]);
                mma16816(oacc[2 * dj + 1], pf[kb], vb[2], vb[3]);
            }
        }

        __syncthreads();
        if (it + 2 < ntiles) LOADKV(it + 2, it & 1);
    }

    l0 += __shfl_xor_sync(0xffffffffu, l0, 1);
    l0 += __shfl_xor_sync(0xffffffffu, l0, 2);
    l1 += __shfl_xor_sync(0xffffffffu, l1, 1);
    l1 += __shfl_xor_sync(0xffffffffu, l1, 2);
    float inv0 = 1.f / l0, inv1 = 1.f / l1;

    const int row0 = q0 + w * 16 + g;
    __half* o0 = O + ((size_t)(b * SS) + row0) * DIM + h * HD;
    __half* o1 = o0 + (size_t)8 * DIM;
    #pragma unroll
    for (int j = 0; j < 16; j++) {
        int col = 8 * j + l4 * 2;
        *(__half2*)&o0[col] = __floats2half2_rn(oacc[j][0] * inv0, oacc[j][1] * inv0);
        *(__half2*)&o1[col] = __floats2half2_rn(oacc[j][2] * inv1, oacc[j][3] * inv1);
    }
}

// ============================================================
extern "C" void kernel_launch(void* const* d_in, const int* in_sizes, int n_in,
                              void* d_out, int out_size) {
    const float* x  = (const float*)d_in[0];
    const float* wq = (const float*)d_in[1];
    const float* wk = (const float*)d_in[2];
    const float* wv = (const float*)d_in[3];
    const float* wo = (const float*)d_in[4];
    const float* fc = (const float*)d_in[5];
    const float* fs = (const float*)d_in[6];
    float* out = (float*)d_out;

    __half *qh, *kh, *vh, *ath, *xh, *wqh, *wkh, *wvh, *woh;
    cudaGetSymbolAddress((void**)&qh,  g_qh);
    cudaGetSymbolAddress((void**)&kh,  g_kh);
    cudaGetSymbolAddress((void**)&vh,  g_vh);
    cudaGetSymbolAddress((void**)&ath, g_ath);
    cudaGetSymbolAddress((void**)&xh,  g_xh);
    cudaGetSymbolAddress((void**)&wqh, g_wqh);
    cudaGetSymbolAddress((void**)&wkh, g_wkh);
    cudaGetSymbolAddress((void**)&wvh, g_wvh);
    cudaGetSymbolAddress((void**)&woh, g_woh);

    const int ATTN_SMEM = (2 * STGH + QT * LDK) * 2;   // 104448 bytes
    cudaFuncSetAttribute(attn_h16, cudaFuncAttributeMaxDynamicSharedMemorySize, ATTN_SMEM);

    // fp16 copies
    cvt_h<<<(MR * DIM / 2 + 255) / 256, 256>>>(x,  xh,  MR * DIM / 2);
    cvt_h<<<((size_t)DIM * DIM / 2 + 255) / 256, 256>>>(wq, wqh, DIM * DIM / 2);
    cvt_h<<<((size_t)KVDIM * DIM / 2 + 255) / 256, 256>>>(wk, wkh, KVDIM * DIM / 2);
    cvt_h<<<((size_t)KVDIM * DIM / 2 + 255) / 256, 256>>>(wv, wvh, KVDIM * DIM / 2);
    cvt_h<<<((size_t)DIM * DIM / 2 + 255) / 256, 256>>>(wo, woh, DIM * DIM / 2);

    // QKV projections with fused RoPE/transpose epilogues (R8 mainloop)
    gemm_f<1><<<dim3(DIM / 128,   MR / 128), 256>>>(xh, wqh, nullptr, qh, fc, fs, MR, DIM,   DIM);
    gemm_f<2><<<dim3(KVDIM / 128, MR / 128), 256>>>(xh, wkh, nullptr, kh, fc, fs, MR, KVDIM, DIM);
    gemm_f<3><<<dim3(KVDIM / 128, MR / 128), 256>>>(xh, wvh, nullptr, vh, fc, fs, MR, KVDIM, DIM);

    // causal GQA attention (fp16 HMMA, fp32 softmax)
    attn_h16<<<dim3(SS / QT, NH, BB), 256, ATTN_SMEM>>>(qh, kh, vh, ath);

    // output projection (fp32 epilogue to d_out)
    gemm_f<0><<<dim3(DIM / 128, MR / 128), 256>>>(ath, woh, out, nullptr, nullptr, nullptr, MR, DIM, DIM);
}

// round 13
// speedup vs baseline: 1.6838x; 1.1350x over previous
#include <cuda_runtime.h>
#include <cuda_fp16.h>
#include <math.h>
#include <cstdint>

#define BB 2
#define SS 2048
#define DIM 4096
#define NH 32
#define NKV 8
#define HD 128
#define MR (BB*SS)          // 4096 rows
#define KVDIM (NKV*HD)      // 1024
#define SCALE 0.08838834764831845f   // 1/sqrt(128)

// ---- scratch (device globals; no allocation allowed) ----
__device__ __half g_qh[(size_t)MR * DIM];     // roped Q fp16 [b][h][s][d] (pre-scaled)
__device__ __half g_kh[(size_t)MR * KVDIM];   // roped K fp16 [b][kvh][s][d]
__device__ __half g_vh[(size_t)MR * KVDIM];   // V fp16 [b][kvh][s][d]
__device__ __half g_ath[(size_t)MR * DIM];    // attn out fp16 [row][h*128+d]
__device__ __half g_xh [(size_t)MR * DIM];    // fp16 copies of inputs
__device__ __half g_wqh[(size_t)DIM * DIM];
__device__ __half g_wkh[(size_t)KVDIM * DIM];
__device__ __half g_wvh[(size_t)KVDIM * DIM];
__device__ __half g_woh[(size_t)DIM * DIM];

// ============================================================
// helpers
// ============================================================
__device__ __forceinline__ uint32_t smem_u32(const void* p) {
    uint32_t a;
    asm("{ .reg .u64 t; cvta.to.shared.u64 t, %1; cvt.u32.u64 %0, t; }" : "=r"(a) : "l"(p));
    return a;
}
__device__ __forceinline__ void cpa16(uint32_t dst, const void* src) {
    asm volatile("cp.async.cg.shared.global [%0], [%1], 16;" :: "r"(dst), "l"(src));
}
#define CP_COMMIT asm volatile("cp.async.commit_group;")
#define CP_WAIT0  asm volatile("cp.async.wait_group 0;")
#define CP_WAIT1  asm volatile("cp.async.wait_group 1;")

__device__ __forceinline__ void ldsm4(uint32_t* r, uint32_t addr) {
    asm volatile("ldmatrix.sync.aligned.m8n8.x4.shared.b16 {%0,%1,%2,%3}, [%4];"
                 : "=r"(r[0]), "=r"(r[1]), "=r"(r[2]), "=r"(r[3]) : "r"(addr));
}
__device__ __forceinline__ void ldsm4t(uint32_t* r, uint32_t addr) {
    asm volatile("ldmatrix.sync.aligned.m8n8.x4.trans.shared.b16 {%0,%1,%2,%3}, [%4];"
                 : "=r"(r[0]), "=r"(r[1]), "=r"(r[2]), "=r"(r[3]) : "r"(addr));
}
__device__ __forceinline__ void mma16816(float* c, const uint32_t* a,
                                         uint32_t b0, uint32_t b1) {
    asm volatile(
        "mma.sync.aligned.m16n8k16.row.col.f32.f16.f16.f32 "
        "{%0,%1,%2,%3}, {%4,%5,%6,%7}, {%8,%9}, {%0,%1,%2,%3};\n"
        : "+f"(c[0]), "+f"(c[1]), "+f"(c[2]), "+f"(c[3])
        : "r"(a[0]), "r"(a[1]), "r"(a[2]), "r"(a[3]), "r"(b0), "r"(b1));
}
__device__ __forceinline__ uint32_t packh2(float a, float b) {
    __half2 h = __floats2half2_rn(a, b);
    return *(uint32_t*)&h;
}

// ============================================================
// fp32 -> fp16 convert
// ============================================================
__global__ void cvt_h(const float* __restrict__ in, __half* __restrict__ out, int n2) {
    int i = blockIdx.x * blockDim.x + threadIdx.x;
    if (i < n2) {
        float2 v = ((const float2*)in)[i];
        ((__half2*)out)[i] = __floats2half2_rn(v.x, v.y);
    }
}

// ============================================================
// fp16 HMMA NT GEMM — BK=64 per stage, 2-stage, dynamic smem.
// Same warp layout / MMA order / epilogues as R12; half the
// iterations -> half the barriers and cp.async waits.
//   EPI 0 = fp32 C row-major (wo proj)
//   EPI 1 = RoPE + scale -> fp16 [b][h(NH)][s][d]   (Q proj)
//   EPI 2 = RoPE         -> fp16 [b][h(NKV)][s][d]  (K proj)
//   EPI 3 = transpose    -> fp16 [b][h(NKV)][s][d]  (V proj)
// ============================================================
#define LDH64 72                       // halves per smem row (64 data + 8 pad)
#define TILE64H (128 * LDH64)          // halves per tile
#define GEMM64_SMEM (4 * TILE64H * 2)  // 2 stages x (A+B), bytes = 73728

template<int EPI>
__global__ __launch_bounds__(256, 2)
void gemm_f(const __half* __restrict__ A, const __half* __restrict__ Bw,
            float* __restrict__ C, __half* __restrict__ Ch,
            const float* __restrict__ fc, const float* __restrict__ fs,
            int M, int N, int K) {
    extern __shared__ __half smg[];
    const int t = threadIdx.x;
    const int bm = blockIdx.y * 128, bn = blockIdx.x * 128;
    const int lane = t & 31, warp = t >> 5;
    const int wm = (warp >> 1) * 32, wn = (warp & 1) * 64;

    const __half* Ag = A  + (size_t)bm * K;
    const __half* Bg = Bw + (size_t)bn * K;

    const uint32_t base = smem_u32(smg);
    const uint32_t sa[2] = { base,                  base + TILE64H * 2 };
    const uint32_t sb[2] = { base + 2 * TILE64H * 2, base + 3 * TILE64H * 2 };

    // loader: per tile 128 rows x 8 chunks(16B) = 1024 chunks; 4 per thread
#define FILL64(buf, kt) do {                                                       \
    uint32_t _a = sa[buf], _b = sb[buf];                                           \
    const __half* _Ak = Ag + (size_t)(kt) * 64;                                    \
    const __half* _Bk = Bg + (size_t)(kt) * 64;                                    \
    _Pragma("unroll")                                                              \
    for (int _i = 0; _i < 4; _i++) {                                               \
        int _id = _i * 256 + t; int _r = _id >> 3, _c = _id & 7;                   \
        cpa16(_a + (_r * LDH64 + _c * 8) * 2, _Ak + (size_t)_r * K + _c * 8);      \
        cpa16(_b + (_r * LDH64 + _c * 8) * 2, _Bk + (size_t)_r * K + _c * 8);      \
    }                                                                              \
    CP_COMMIT; } while (0)

    float acc[2][8][4];
    #pragma unroll
    for (int mi = 0; mi < 2; mi++)
        #pragma unroll
        for (int ni = 0; ni < 8; ni++)
            #pragma unroll
            for (int j = 0; j < 4; j++) acc[mi][ni][j] = 0.f;

    const int niter = K >> 6;    // K/64
    FILL64(0, 0);

    for (int it = 0; it < niter; it++) {
        const int buf = it & 1;
        CP_WAIT0;
        __syncthreads();
        if (it + 1 < niter) FILL64(buf ^ 1, it + 1);

        const uint32_t pa = sa[buf], pb = sb[buf];

        #pragma unroll
        for (int ks = 0; ks < 4; ks++) {          // four k16 steps
            uint32_t a[2][4];
            #pragma unroll
            for (int mi = 0; mi < 2; mi++) {
                uint32_t addr = pa + (((wm + mi * 16 + (lane & 15)) * LDH64) +
                                      (2 * ks + (lane >> 4)) * 8) * 2;
                ldsm4(a[mi], addr);
            }
            uint32_t b[4][4];
            #pragma unroll
            for (int np = 0; np < 4; np++) {
                uint32_t addr = pb + (((wn + np * 16 + (lane & 15)) * LDH64) +
                                      (2 * ks + (lane >> 4)) * 8) * 2;
                ldsm4(b[np], addr);
            }
            #pragma unroll
            for (int mi = 0; mi < 2; mi++)
                #pragma unroll
                for (int np = 0; np < 4; np++) {
                    mma16816(acc[mi][np * 2],     a[mi], b[np][0], b[np][2]);
                    mma16816(acc[mi][np * 2 + 1], a[mi], b[np][1], b[np][3]);
                }
        }
        __syncthreads();
    }

    const int g = lane >> 2, l4 = lane & 3;
    if (EPI == 0) {
        #pragma unroll
        for (int mi = 0; mi < 2; mi++)
            #pragma unroll
            for (int ni = 0; ni < 8; ni++) {
                const int rr = bm + wm + mi * 16 + g;
                const int cc = bn + wn + ni * 8 + l4 * 2;
                *(float2*)&C[(size_t)rr * N + cc]       = make_float2(acc[mi][ni][0], acc[mi][ni][1]);
                *(float2*)&C[(size_t)(rr + 8) * N + cc] = make_float2(acc[mi][ni][2], acc[mi][ni][3]);
            }
    } else {
        const int nh = (EPI == 1) ? NH : NKV;
        #pragma unroll
        for (int mi = 0; mi < 2; mi++)
            #pragma unroll
            for (int ni = 0; ni < 8; ni++) {
                const int rr = bm + wm + mi * 16 + g;
                const int cc = bn + wn + ni * 8 + l4 * 2;
                const int hh = cc >> 7, d = cc & 127, p = d >> 1;
                #pragma unroll
                for (int hf = 0; hf < 2; hf++) {
                    const int row = rr + 8 * hf;
                    const int s = row & (SS - 1), b = row >> 11;
                    float x0 = acc[mi][ni][2 * hf], x1 = acc[mi][ni][2 * hf + 1];
                    if (EPI != 3) {
                        float cv = fc[s * 64 + p], sv = fs[s * 64 + p];
                        float y0 = x0 * cv - x1 * sv;
                        float y1 = x0 * sv + x1 * cv;
                        if (EPI == 1) { y0 *= SCALE; y1 *= SCALE; }
                        x0 = y0; x1 = y1;
                    }
                    *(__half2*)&Ch[(((size_t)(b * nh + hh)) * SS + s) * HD + d] =
                        __floats2half2_rn(x0, x1);
                }
            }
    }
}

// ============================================================
// fp16 HMMA flash attention (unchanged from R8/R12, passing).
// Q tile 128 (8 warps x 16 rows), KV tile 64, double-buffered K/V.
// ============================================================
#define QT 128
#define KT 64
#define LDK 136
#define STGH (2 * KT * LDK)

__global__ __launch_bounds__(256, 1)
void attn_h16(const __half* __restrict__ Q, const __half* __restrict__ K,
              const __half* __restrict__ V, __half* __restrict__ O) {
    extern __shared__ __half sm[];
    const int t = threadIdx.x, lane = t & 31, w = t >> 5;
    const int l4 = lane & 3, g = lane >> 2, lr = lane & 15, lc = lane >> 4;
    const int qt = blockIdx.x, h = blockIdx.y, b = blockIdx.z;
    const int kvh = h >> 2, q0 = qt * QT;
    const __half* qg = Q + ((size_t)(b * NH + h) * SS + q0) * HD;
    const __half* kg = K + ((size_t)(b * NKV + kvh) * SS) * HD;
    const __half* vg = V + ((size_t)(b * NKV + kvh) * SS) * HD;
    const uint32_t smb = smem_u32(sm);
    const uint32_t qsm = smb + 2 * STGH * 2;

    for (int i = t; i < 2048; i += 256) {
        int r = i >> 4, c = i & 15;
        cpa16(qsm + (r * LDK + c * 8) * 2, qg + (size_t)r * HD + c * 8);
    }
    CP_COMMIT;

#define LOADKV(tile, buf) do {                                                  \
    uint32_t _k = smb + (buf) * STGH * 2;                                       \
    uint32_t _v = _k + KT * LDK * 2;                                            \
    const __half* _gk = kg + (size_t)(tile) * KT * HD;                          \
    const __half* _gv = vg + (size_t)(tile) * KT * HD;                          \
    _Pragma("unroll")                                                           \
    for (int _i = 0; _i < 4; _i++) {                                            \
        int _id = _i * 256 + t; int _r = _id >> 4, _c = _id & 15;               \
        cpa16(_k + (_r * LDK + _c * 8) * 2, _gk + (size_t)_r * HD + _c * 8);    \
        cpa16(_v + (_r * LDK + _c * 8) * 2, _gv + (size_t)_r * HD + _c * 8);    \
    }                                                                           \
    CP_COMMIT; } while (0)

    const int ntiles = q0 / KT + 2;
    LOADKV(0, 0);

    CP_WAIT1;
    __syncthreads();

    uint32_t qf_[8][4];
    #pragma unroll
    for (int ks = 0; ks < 8; ks++)
        ldsm4(qf_[ks], qsm + ((w * 16 + lr) * LDK + ks * 16 + lc * 8) * 2);

    if (ntiles > 1) LOADKV(1, 1);

    float mx0 = -INFINITY, mx1 = -INFINITY, l0 = 0.f, l1 = 0.f;
    float oacc[16][4];
    #pragma unroll
    for (int j = 0; j < 16; j++)
        #pragma unroll
        for (int e = 0; e < 4; e++) oacc[j][e] = 0.f;

    for (int it = 0; it < ntiles; it++) {
        if (it + 1 < ntiles) { CP_WAIT1; } else { CP_WAIT0; }
        __syncthreads();
        const uint32_t bK = smb + (it & 1) * STGH * 2;
        const uint32_t bV = bK + KT * LDK * 2;
        const int kv0 = it * KT;

        float sc[8][4];
        #pragma unroll
        for (int f = 0; f < 8; f++)
            #pragma unroll
            for (int e = 0; e < 4; e++) sc[f][e] = 0.f;

        #pragma unroll
        for (int ks = 0; ks < 8; ks++) {
            #pragma unroll
            for (int np = 0; np < 4; np++) {
                uint32_t kb4[4];
                ldsm4(kb4, bK + ((np * 16 + lr) * LDK + ks * 16 + lc * 8) * 2);
                mma16816(sc[2 * np],     qf_[ks], kb4[0], kb4[2]);
                mma16816(sc[2 * np + 1], qf_[ks], kb4[1], kb4[3]);
            }
        }

        const int row0 = q0 + w * 16 + g;
        if (kv0 + KT - 1 > q0 + w * 16) {
            #pragma unroll
            for (int f = 0; f < 8; f++) {
                int c = kv0 + 8 * f + l4 * 2;
                if (c     > row0)     sc[f][0] = -1e30f;
                if (c + 1 > row0)     sc[f][1] = -1e30f;
                if (c     > row0 + 8) sc[f][2] = -1e30f;
                if (c + 1 > row0 + 8) sc[f][3] = -1e30f;
            }
        }

        float m0 = -INFINITY, m1 = -INFINITY;
        #pragma unroll
        for (int f = 0; f < 8; f++) {
            m0 = fmaxf(m0, fmaxf(sc[f][0], sc[f][1]));
            m1 = fmaxf(m1, fmaxf(sc[f][2], sc[f][3]));
        }
        m0 = fmaxf(m0, __shfl_xor_sync(0xffffffffu, m0, 1));
        m0 = fmaxf(m0, __shfl_xor_sync(0xffffffffu, m0, 2));
        m1 = fmaxf(m1, __shfl_xor_sync(0xffffffffu, m1, 1));
        m1 = fmaxf(m1, __shfl_xor_sync(0xffffffffu, m1, 2));
        float nm0 = fmaxf(mx0, m0), nm1 = fmaxf(mx1, m1);
        float cs0 = __expf(mx0 - nm0), cs1 = __expf(mx1 - nm1);
        mx0 = nm0; mx1 = nm1;

        float ps0 = 0.f, ps1 = 0.f;
        #pragma unroll
        for (int f = 0; f < 8; f++) {
            sc[f][0] = __expf(sc[f][0] - nm0);
            sc[f][1] = __expf(sc[f][1] - nm0);
            sc[f][2] = __expf(sc[f][2] - nm1);
            sc[f][3] = __expf(sc[f][3] - nm1);
            ps0 += sc[f][0] + sc[f][1];
            ps1 += sc[f][2] + sc[f][3];
        }
        l0 = l0 * cs0 + ps0;
        l1 = l1 * cs1 + ps1;
        #pragma unroll
        for (int j = 0; j < 16; j++) {
            oacc[j][0] *= cs0; oacc[j][1] *= cs0;
            oacc[j][2] *= cs1; oacc[j][3] *= cs1;
        }

        uint32_t pf[4][4];
        #pragma unroll
        for (int kb = 0; kb < 4; kb++) {
            pf[kb][0] = packh2(sc[2 * kb][0],     sc[2 * kb][1]);
            pf[kb][1] = packh2(sc[2 * kb][2],     sc[2 * kb][3]);
            pf[kb][2] = packh2(sc[2 * kb + 1][0], sc[2 * kb + 1][1]);
            pf[kb][3] = packh2(sc[2 * kb + 1][2], sc[2 * kb + 1][3]);
        }

        #pragma unroll
        for (int kb = 0; kb < 4; kb++) {
            #pragma unroll
            for (int dj = 0; dj < 8; dj++) {
                uint32_t vb[4];
                ldsm4t(vb, bV + ((kb * 16 + lr) * LDK + dj * 16 + lc * 8) * 2);
                mma16816(oacc[2 * dj],     pf[kb], vb[0], vb[1]);
                mma16816(oacc[2 * dj + 1], pf[kb], vb[2], vb[3]);
            }
        }

        __syncthreads();
        if (it + 2 < ntiles) LOADKV(it + 2, it & 1);
    }

    l0 += __shfl_xor_sync(0xffffffffu, l0, 1);
    l0 += __shfl_xor_sync(0xffffffffu, l0, 2);
    l1 += __shfl_xor_sync(0xffffffffu, l1, 1);
    l1 += __shfl_xor_sync(0xffffffffu, l1, 2);
    float inv0 = 1.f / l0, inv1 = 1.f / l1;

    const int row0 = q0 + w * 16 + g;
    __half* o0 = O + ((size_t)(b * SS) + row0) * DIM + h * HD;
    __half* o1 = o0 + (size_t)8 * DIM;
    #pragma unroll
    for (int j = 0; j < 16; j++) {
        int col = 8 * j + l4 * 2;
        *(__half2*)&o0[col] = __floats2half2_rn(oacc[j][0] * inv0, oacc[j][1] * inv0);
        *(__half2*)&o1[col] = __floats2half2_rn(oacc[j][2] * inv1, oacc[j][3] * inv1);
    }
}

// ============================================================
extern "C" void kernel_launch(void* const* d_in, const int* in_sizes, int n_in,
                              void* d_out, int out_size) {
    const float* x  = (const float*)d_in[0];
    const float* wq = (const float*)d_in[1];
    const float* wk = (const float*)d_in[2];
    const float* wv = (const float*)d_in[3];
    const float* wo = (const float*)d_in[4];
    const float* fc = (const float*)d_in[5];
    const float* fs = (const float*)d_in[6];
    float* out = (float*)d_out;

    __half *qh, *kh, *vh, *ath, *xh, *wqh, *wkh, *wvh, *woh;
    cudaGetSymbolAddress((void**)&qh,  g_qh);
    cudaGetSymbolAddress((void**)&kh,  g_kh);
    cudaGetSymbolAddress((void**)&vh,  g_vh);
    cudaGetSymbolAddress((void**)&ath, g_ath);
    cudaGetSymbolAddress((void**)&xh,  g_xh);
    cudaGetSymbolAddress((void**)&wqh, g_wqh);
    cudaGetSymbolAddress((void**)&wkh, g_wkh);
    cudaGetSymbolAddress((void**)&wvh, g_wvh);
    cudaGetSymbolAddress((void**)&woh, g_woh);

    const int ATTN_SMEM = (2 * STGH + QT * LDK) * 2;   // 104448 bytes
    cudaFuncSetAttribute(attn_h16, cudaFuncAttributeMaxDynamicSharedMemorySize, ATTN_SMEM);
    cudaFuncSetAttribute(gemm_f<0>, cudaFuncAttributeMaxDynamicSharedMemorySize, GEMM64_SMEM);
    cudaFuncSetAttribute(gemm_f<1>, cudaFuncAttributeMaxDynamicSharedMemorySize, GEMM64_SMEM);
    cudaFuncSetAttribute(gemm_f<2>, cudaFuncAttributeMaxDynamicSharedMemorySize, GEMM64_SMEM);
    cudaFuncSetAttribute(gemm_f<3>, cudaFuncAttributeMaxDynamicSharedMemorySize, GEMM64_SMEM);

    // fp16 copies
    cvt_h<<<(MR * DIM / 2 + 255) / 256, 256>>>(x,  xh,  MR * DIM / 2);
    cvt_h<<<((size_t)DIM * DIM / 2 + 255) / 256, 256>>>(wq, wqh, DIM * DIM / 2);
    cvt_h<<<((size_t)KVDIM * DIM / 2 + 255) / 256, 256>>>(wk, wkh, KVDIM * DIM / 2);
    cvt_h<<<((size_t)KVDIM * DIM / 2 + 255) / 256, 256>>>(wv, wvh, KVDIM * DIM / 2);
    cvt_h<<<((size_t)DIM * DIM / 2 + 255) / 256, 256>>>(wo, woh, DIM * DIM / 2);

    // QKV projections with fused RoPE/transpose epilogues (BK=64 mainloop)
    gemm_f<1><<<dim3(DIM / 128,   MR / 128), 256, GEMM64_SMEM>>>(xh, wqh, nullptr, qh, fc, fs, MR, DIM,   DIM);
    gemm_f<2><<<dim3(KVDIM / 128, MR / 128), 256, GEMM64_SMEM>>>(xh, wkh, nullptr, kh, fc, fs, MR, KVDIM, DIM);
    gemm_f<3><<<dim3(KVDIM / 128, MR / 128), 256, GEMM64_SMEM>>>(xh, wvh, nullptr, vh, fc, fs, MR, KVDIM, DIM);

    // causal GQA attention (fp16 HMMA, fp32 softmax)
    attn_h16<<<dim3(SS / QT, NH, BB), 256, ATTN_SMEM>>>(qh, kh, vh, ath);

    // output projection (fp32 epilogue to d_out)
    gemm_f<0><<<dim3(DIM / 128, MR / 128), 256, GEMM64_SMEM>>>(ath, woh, out, nullptr, nullptr, nullptr, MR, DIM, DIM);
}